// round 2
// baseline (speedup 1.0000x reference)
#include <cuda_runtime.h>
#include <cstdint>

typedef unsigned long long ull;

// ---------------- problem constants ----------------
#define TOK_LABEL   2
#define ACT_START   5
#define TIME_START  69
#define NB          8
#define NT_SEQ      2048
#define ND          1024
#define N_ACT       64
#define N_TIME      32
#define N_COLS      96
#define M_TOT       (NB * NT_SEQ)
#define ACT_ELEMS   ((size_t)M_TOT * N_ACT)

// ---------------- scratch ----------------
__device__ float g_Wc[N_COLS * ND];
__device__ float g_bc[N_COLS];
__device__ int   g_qlist[NB][NT_SEQ];
__device__ int   g_klist[NB][NT_SEQ];
__device__ int   g_kcls [NB][NT_SEQ];
__device__ int   g_qcnt[NB];
__device__ int   g_kcnt[NB];
__device__ float g_qrn[NB][NT_SEQ];   // 1/norm for query rows
__device__ float g_krn[NB][NT_SEQ];   // 1/norm for key rows

// ---------------- helpers ----------------
__device__ __forceinline__ float softplus_f(float x) {
    return (x > 20.0f) ? x : log1pf(expf(x));
}
__device__ __forceinline__ ull pack2(float x, float y) {
    ull r; asm("mov.b64 %0, {%1,%2};" : "=l"(r) : "f"(x), "f"(y)); return r;
}
__device__ __forceinline__ float2 unpack2(ull v) {
    float2 r; asm("mov.b64 {%0,%1}, %2;" : "=f"(r.x), "=f"(r.y) : "l"(v)); return r;
}
__device__ __forceinline__ void fma2(ull& d, ull a, ull b) {
    asm("fma.rn.f32x2 %0, %1, %2, %0;" : "+l"(d) : "l"(a), "l"(b));
}

// ---------------- kernel 1: fused weight-fold + token scan ----------------
#define WC_BLOCKS 384   // 96*1024 / 256

__global__ void prep_kernel(const float* __restrict__ E,
                            const float* __restrict__ Wn, const float* __restrict__ bn,
                            const float* __restrict__ Wt, const float* __restrict__ bt,
                            const float* __restrict__ tsa, const float* __restrict__ tst,
                            const int* __restrict__ tokens) {
    if (blockIdx.x < WC_BLOCKS) {
        int i = blockIdx.x * blockDim.x + threadIdx.x;
        float sa = softplus_f(*tsa);
        float st = softplus_f(*tst);
        int r = i >> 10;
        int c = i & (ND - 1);
        float v;
        if (r < N_ACT)
            v = Wn[r * ND + c] + sa * E[(ACT_START + r) * ND + c];
        else
            v = Wt[(r - N_ACT) * ND + c] + st * E[(TIME_START + (r - N_ACT)) * ND + c];
        g_Wc[i] = v;
        if (i < N_COLS)
            g_bc[i] = (i < N_ACT) ? bn[i] : bt[i - N_ACT];
        return;
    }
    // scan blocks: one per batch
    int b    = blockIdx.x - WC_BLOCKS;
    int lane = threadIdx.x & 31;
    int warp = threadIdx.x >> 5;
    const int* tk = tokens + b * NT_SEQ;

    if (warp == 0) {
        int cnt = 0;
        for (int base = 0; base < NT_SEQ; base += 32) {
            int pos = base + lane;
            bool p = (tk[pos] == TOK_LABEL);
            unsigned m = __ballot_sync(0xffffffffu, p);
            if (p) g_qlist[b][cnt + __popc(m & ((1u << lane) - 1u))] = pos;
            cnt += __popc(m);
        }
        if (lane == 0) g_qcnt[b] = cnt;
    } else if (warp == 1) {
        int cnt = 0;
        for (int base = 0; base < NT_SEQ; base += 32) {
            int pos = base + lane;
            int tok = tk[pos];
            bool p = (pos >= 1) && (tk[pos - 1] == TOK_LABEL) && (tok >= ACT_START);
            unsigned m = __ballot_sync(0xffffffffu, p);
            if (p) {
                int r = cnt + __popc(m & ((1u << lane) - 1u));
                g_klist[b][r] = pos;
                g_kcls[b][r]  = (tok < TIME_START) ? (tok - ACT_START)
                                                   : (N_ACT + (tok - TIME_START));
            }
            cnt += __popc(m);
        }
        if (lane == 0) g_kcnt[b] = cnt;
    }
}

// ---------------- kernel 2: reciprocal norms of listed rows ----------------
// one warp per block; grid (256, NB)
__global__ void norm_kernel(const float* __restrict__ h) {
    int b    = blockIdx.y;
    int lane = threadIdx.x;
    const float* hb = h + (size_t)b * NT_SEQ * ND;

    for (int pass = 0; pass < 2; pass++) {
        int cnt = pass ? g_kcnt[b] : g_qcnt[b];
        const int* lst = pass ? g_klist[b] : g_qlist[b];
        float* outp = pass ? g_krn[b] : g_qrn[b];
        for (int i = blockIdx.x; i < cnt; i += gridDim.x) {
            const float* row = hb + (size_t)lst[i] * ND;
            float s = 0.0f;
            #pragma unroll
            for (int c = 0; c < 8; c++) {
                float4 v = *(const float4*)(row + c * 128 + lane * 4);
                s += v.x*v.x + v.y*v.y + v.z*v.z + v.w*v.w;
            }
            #pragma unroll
            for (int o = 16; o; o >>= 1) s += __shfl_xor_sync(0xffffffffu, s, o);
            if (lane == 0) outp[i] = 1.0f / fmaxf(sqrtf(s), 1e-12f);
        }
    }
}

// ---------------- kernel 3: 16384x96x1024 fp32 GEMM, f32x2, row-pair accum ----------------
#define BM 128
#define BK 32
#define SA 130          // even -> aligned LDS.64; conflict-light stores
#define SB 224          // 16 tx-groups * 14 floats (12 data + 2 pad) -> conflict-free
#define NTILES (ND / BK)

__global__ __launch_bounds__(256, 1)
void gemm_kernel(const float* __restrict__ h, float* __restrict__ out) {
    __shared__ __align__(16) float As[BK * SA];   // [k][m], row-pairs natural
    __shared__ __align__(16) float Bs[BK * SB];   // [k][col dup pairs]

    const int tid = threadIdx.x;
    const int m0  = blockIdx.x * BM;
    const int tx  = tid & 15;          // cols tx*6 .. tx*6+5
    const int ty  = tid >> 4;          // rows ty*8 .. ty*8+7 (4 pairs)

    const int c4  = tid & 7;           // k-subgroup for loads
    const int rA  = tid >> 3;          // base row / base col for loads

    ull acc[24];
    #pragma unroll
    for (int i = 0; i < 24; i++) acc[i] = 0ull;

    float4 pa[4], pb[3];

    const float* gA = h + (size_t)(m0 + rA) * ND + c4 * 4;
    const float* gB = g_Wc + (size_t)rA * ND + c4 * 4;

    // B store addressing (n = rA + 32r)
    int tgr[3], crr[3];
    #pragma unroll
    for (int r = 0; r < 3; r++) { int n = rA + 32 * r; tgr[r] = n / 6; crr[r] = n - tgr[r] * 6; }

    // prologue: tile 0 loads
    #pragma unroll
    for (int r = 0; r < 4; r++) pa[r] = *(const float4*)(gA + (size_t)(32 * r) * ND);
    #pragma unroll
    for (int r = 0; r < 3; r++) pb[r] = *(const float4*)(gB + (size_t)(32 * r) * ND);

    for (int t = 0; t < NTILES; t++) {
        // store prefetched tile into smem
        #pragma unroll
        for (int r = 0; r < 4; r++) {
            int row = rA + 32 * r;
            As[(c4 * 4 + 0) * SA + row] = pa[r].x;
            As[(c4 * 4 + 1) * SA + row] = pa[r].y;
            As[(c4 * 4 + 2) * SA + row] = pa[r].z;
            As[(c4 * 4 + 3) * SA + row] = pa[r].w;
        }
        #pragma unroll
        for (int r = 0; r < 3; r++) {
            int boff = tgr[r] * 14 + crr[r] * 2;
            *(ull*)&Bs[(c4 * 4 + 0) * SB + boff] = pack2(pb[r].x, pb[r].x);
            *(ull*)&Bs[(c4 * 4 + 1) * SB + boff] = pack2(pb[r].y, pb[r].y);
            *(ull*)&Bs[(c4 * 4 + 2) * SB + boff] = pack2(pb[r].z, pb[r].z);
            *(ull*)&Bs[(c4 * 4 + 3) * SB + boff] = pack2(pb[r].w, pb[r].w);
        }
        __syncthreads();

        // prefetch next tile
        if (t + 1 < NTILES) {
            const float* a2 = gA + (size_t)(t + 1) * BK;
            const float* b2 = gB + (size_t)(t + 1) * BK;
            #pragma unroll
            for (int r = 0; r < 4; r++) pa[r] = *(const float4*)(a2 + (size_t)(32 * r) * ND);
            #pragma unroll
            for (int r = 0; r < 3; r++) pb[r] = *(const float4*)(b2 + (size_t)(32 * r) * ND);
        }

        // compute
        #pragma unroll 8
        for (int k = 0; k < BK; k++) {
            const float* ar = &As[k * SA + ty * 8];
            const float* br = &Bs[k * SB + tx * 14];
            ull av[4], bv[6];
            #pragma unroll
            for (int i = 0; i < 4; i++) av[i] = *(const ull*)(ar + 2 * i);
            #pragma unroll
            for (int j = 0; j < 6; j++) bv[j] = *(const ull*)(br + 2 * j);
            #pragma unroll
            for (int i = 0; i < 4; i++)
                #pragma unroll
                for (int j = 0; j < 6; j++)
                    fma2(acc[i * 6 + j], av[i], bv[j]);
        }
        __syncthreads();
    }

    // epilogue
    float* out_time = out + ACT_ELEMS;
    #pragma unroll
    for (int i = 0; i < 4; i++) {
        size_t r0 = (size_t)m0 + ty * 8 + 2 * i;
        #pragma unroll
        for (int j = 0; j < 6; j++) {
            int col = tx * 6 + j;
            float2 v = unpack2(acc[i * 6 + j]);
            float bias = g_bc[col];
            if (col < N_ACT) {
                out[r0 * N_ACT + col]       = v.x + bias;
                out[(r0 + 1) * N_ACT + col] = v.y + bias;
            } else {
                int ct = col - N_ACT;
                out_time[r0 * N_TIME + ct]       = v.x + bias;
                out_time[(r0 + 1) * N_TIME + ct] = v.y + bias;
            }
        }
    }
}

// ---------------- kernel 4: retrieval/copy head, warp-per-key ----------------
__global__ __launch_bounds__(256)
void copy_kernel(const float* __restrict__ h, float* __restrict__ out,
                 const float* __restrict__ csa, const float* __restrict__ cst,
                 const float* __restrict__ cta, const float* __restrict__ ctt) {
    const int b    = blockIdx.y;
    const int tid  = threadIdx.x;
    const int warp = tid >> 5;
    const int lane = tid & 31;
    const int qcnt = g_qcnt[b];
    const int kc   = g_kcnt[b];

    __shared__ float s_acc[N_COLS];

    const float tau_a = softplus_f(*cta);
    const float tau_t = softplus_f(*ctt);
    const float sca   = softplus_f(*csa);
    const float sct   = softplus_f(*cst);
    const float* hb   = h + (size_t)b * NT_SEQ * ND;

    for (int qi = blockIdx.x; qi < qcnt; qi += gridDim.x) {
        __syncthreads();
        if (tid < N_COLS) s_acc[tid] = 0.0f;
        const int q = g_qlist[b][qi];
        const float rnq = g_qrn[b][qi];
        const float* hq = hb + (size_t)q * ND;
        float4 qv[8];
        #pragma unroll
        for (int c = 0; c < 8; c++) qv[c] = *(const float4*)(hq + c * 128 + lane * 4);
        __syncthreads();

        for (int j = warp; j < kc; j += 8) {
            int k = g_klist[b][j];
            if (k >= q) continue;                 // strict past
            const float* hk = hb + (size_t)k * ND;
            float dot = 0.0f;
            #pragma unroll
            for (int c = 0; c < 8; c++) {
                float4 kv = *(const float4*)(hk + c * 128 + lane * 4);
                dot += qv[c].x * kv.x + qv[c].y * kv.y + qv[c].z * kv.z + qv[c].w * kv.w;
            }
            #pragma unroll
            for (int o = 16; o; o >>= 1) dot += __shfl_xor_sync(0xffffffffu, dot, o);
            if (lane == 0) {
                int cls = g_kcls[b][j];
                float val = dot * rnq * g_krn[b][j] * (cls < N_ACT ? tau_a : tau_t);
                atomicAdd(&s_acc[cls], val);
            }
        }
        __syncthreads();

        size_t m = (size_t)b * NT_SEQ + q;
        if (tid < N_ACT) {
            out[m * N_ACT + tid] += sca * s_acc[tid];
        } else if (tid < N_COLS) {
            float* out_time = out + ACT_ELEMS;
            out_time[m * N_TIME + (tid - N_ACT)] += sct * s_acc[tid];
        }
    }
}

// ---------------- launch ----------------
extern "C" void kernel_launch(void* const* d_in, const int* in_sizes, int n_in,
                              void* d_out, int out_size) {
    const int*   tokens = (const int*)  d_in[0];
    const float* h      = (const float*)d_in[1];
    const float* E      = (const float*)d_in[2];
    const float* Wn     = (const float*)d_in[3];
    const float* bn     = (const float*)d_in[4];
    const float* Wt     = (const float*)d_in[5];
    const float* bt     = (const float*)d_in[6];
    const float* tsa    = (const float*)d_in[7];
    const float* tst    = (const float*)d_in[8];
    const float* csa    = (const float*)d_in[9];
    const float* cst    = (const float*)d_in[10];
    const float* cta    = (const float*)d_in[11];
    const float* ctt    = (const float*)d_in[12];
    float* out = (float*)d_out;

    prep_kernel<<<WC_BLOCKS + NB, 256>>>(E, Wn, bn, Wt, bt, tsa, tst, tokens);
    norm_kernel<<<dim3(256, NB), 32>>>(h);
    gemm_kernel<<<M_TOT / BM, 256>>>(h, out);
    copy_kernel<<<dim3(64, NB), 256>>>(h, out, csa, cst, cta, ctt);
}

// round 4
// speedup vs baseline: 1.3175x; 1.3175x over previous
#include <cuda_runtime.h>
#include <cuda_bf16.h>
#include <cstdint>

typedef unsigned long long ull;

// ---------------- problem constants ----------------
#define TOK_LABEL   2
#define ACT_START   5
#define TIME_START  69
#define NB          8
#define NT_SEQ      2048
#define ND          1024
#define N_ACT       64
#define N_TIME      32
#define N_COLS      96
#define M_TOT       (NB * NT_SEQ)
#define ACT_ELEMS   ((size_t)M_TOT * N_ACT)

// GEMM tiling
#define BM       128
#define BK       32
#define NTILES   (ND / BK)     // 32
#define ASTR     40            // smem row stride (bf16 elems): 80B rows -> ldmatrix conflict-free
#define BSTR     40

// ---------------- scratch ----------------
__device__ __align__(16) __nv_bfloat16 g_Bhi[N_COLS * ND];
__device__ __align__(16) __nv_bfloat16 g_Blo[N_COLS * ND];
__device__ int   g_qlist[NB][NT_SEQ];
__device__ int   g_klist[NB][NT_SEQ];
__device__ int   g_kcls [NB][NT_SEQ];
__device__ int   g_qcnt[NB];
__device__ int   g_kcnt[NB];
__device__ float g_qrn[NB][NT_SEQ];
__device__ float g_krn[NB][NT_SEQ];

// ---------------- helpers ----------------
__device__ __forceinline__ float softplus_f(float x) {
    return (x > 20.0f) ? x : log1pf(expf(x));
}
__device__ __forceinline__ uint32_t smem_u32(const void* p) {
    uint32_t a;
    asm("{ .reg .u64 t; cvta.to.shared.u64 t, %1; cvt.u32.u64 %0, t; }" : "=r"(a) : "l"(p));
    return a;
}
__device__ __forceinline__ void ldsm4(uint32_t* r, uint32_t addr) {
    asm volatile("ldmatrix.sync.aligned.m8n8.x4.shared.b16 {%0,%1,%2,%3}, [%4];"
                 : "=r"(r[0]), "=r"(r[1]), "=r"(r[2]), "=r"(r[3]) : "r"(addr));
}
__device__ __forceinline__ void mma_bf16(float* c, const uint32_t* a, const uint32_t* b) {
    asm volatile(
        "mma.sync.aligned.m16n8k16.row.col.f32.bf16.bf16.f32 "
        "{%0,%1,%2,%3}, {%4,%5,%6,%7}, {%8,%9}, {%0,%1,%2,%3};"
        : "+f"(c[0]), "+f"(c[1]), "+f"(c[2]), "+f"(c[3])
        : "r"(a[0]), "r"(a[1]), "r"(a[2]), "r"(a[3]), "r"(b[0]), "r"(b[1]));
}
// split 8 fp32 -> 8 bf16 hi (uint4) + 8 bf16 lo (uint4)
__device__ __forceinline__ void split8(const float* g, uint4& hi, uint4& lo) {
    float4 v0 = *(const float4*)g;
    float4 v1 = *(const float4*)(g + 4);
    float f[8] = {v0.x, v0.y, v0.z, v0.w, v1.x, v1.y, v1.z, v1.w};
    uint32_t h[4], l[4];
    #pragma unroll
    for (int i = 0; i < 4; i++) {
        __nv_bfloat16 h0 = __float2bfloat16(f[2 * i]);
        __nv_bfloat16 h1 = __float2bfloat16(f[2 * i + 1]);
        __nv_bfloat16 l0 = __float2bfloat16(f[2 * i] - __bfloat162float(h0));
        __nv_bfloat16 l1 = __float2bfloat16(f[2 * i + 1] - __bfloat162float(h1));
        h[i] = (uint32_t)__bfloat16_as_ushort(h0) | ((uint32_t)__bfloat16_as_ushort(h1) << 16);
        l[i] = (uint32_t)__bfloat16_as_ushort(l0) | ((uint32_t)__bfloat16_as_ushort(l1) << 16);
    }
    hi = make_uint4(h[0], h[1], h[2], h[3]);
    lo = make_uint4(l[0], l[1], l[2], l[3]);
}

// ---------------- kernel 1: weight-fold (-> bf16 hi/lo) + token scan ----------------
#define WC_BLOCKS 384   // 96*1024 / 256

__global__ void prep_kernel(const float* __restrict__ E,
                            const float* __restrict__ Wn,
                            const float* __restrict__ Wt,
                            const float* __restrict__ tsa, const float* __restrict__ tst,
                            const int* __restrict__ tokens) {
    if (blockIdx.x < WC_BLOCKS) {
        int i = blockIdx.x * blockDim.x + threadIdx.x;
        float sa = softplus_f(*tsa);
        float st = softplus_f(*tst);
        int r = i >> 10;
        int c = i & (ND - 1);
        float v;
        if (r < N_ACT)
            v = Wn[r * ND + c] + sa * E[(ACT_START + r) * ND + c];
        else
            v = Wt[(r - N_ACT) * ND + c] + st * E[(TIME_START + (r - N_ACT)) * ND + c];
        __nv_bfloat16 hb = __float2bfloat16(v);
        g_Bhi[i] = hb;
        g_Blo[i] = __float2bfloat16(v - __bfloat162float(hb));
        return;
    }
    int b    = blockIdx.x - WC_BLOCKS;
    int lane = threadIdx.x & 31;
    int warp = threadIdx.x >> 5;
    const int* tk = tokens + b * NT_SEQ;

    if (warp == 0) {
        int cnt = 0;
        for (int base = 0; base < NT_SEQ; base += 32) {
            int pos = base + lane;
            bool p = (tk[pos] == TOK_LABEL);
            unsigned m = __ballot_sync(0xffffffffu, p);
            if (p) g_qlist[b][cnt + __popc(m & ((1u << lane) - 1u))] = pos;
            cnt += __popc(m);
        }
        if (lane == 0) g_qcnt[b] = cnt;
    } else if (warp == 1) {
        int cnt = 0;
        for (int base = 0; base < NT_SEQ; base += 32) {
            int pos = base + lane;
            int tok = tk[pos];
            bool p = (pos >= 1) && (tk[pos - 1] == TOK_LABEL) && (tok >= ACT_START);
            unsigned m = __ballot_sync(0xffffffffu, p);
            if (p) {
                int r = cnt + __popc(m & ((1u << lane) - 1u));
                g_klist[b][r] = pos;
                g_kcls[b][r]  = (tok < TIME_START) ? (tok - ACT_START)
                                                   : (N_ACT + (tok - TIME_START));
            }
            cnt += __popc(m);
        }
        if (lane == 0) g_kcnt[b] = cnt;
    }
}

// ---------------- kernel 2: reciprocal norms of listed rows ----------------
__global__ void norm_kernel(const float* __restrict__ h) {
    int b    = blockIdx.y;
    int lane = threadIdx.x;
    const float* hb = h + (size_t)b * NT_SEQ * ND;

    for (int pass = 0; pass < 2; pass++) {
        int cnt = pass ? g_kcnt[b] : g_qcnt[b];
        const int* lst = pass ? g_klist[b] : g_qlist[b];
        float* outp = pass ? g_krn[b] : g_qrn[b];
        for (int i = blockIdx.x; i < cnt; i += gridDim.x) {
            const float* row = hb + (size_t)lst[i] * ND;
            float s = 0.0f;
            #pragma unroll
            for (int c = 0; c < 8; c++) {
                float4 v = *(const float4*)(row + c * 128 + lane * 4);
                s += v.x*v.x + v.y*v.y + v.z*v.z + v.w*v.w;
            }
            #pragma unroll
            for (int o = 16; o; o >>= 1) s += __shfl_xor_sync(0xffffffffu, s, o);
            if (lane == 0) outp[i] = 1.0f / fmaxf(sqrtf(s), 1e-12f);
        }
    }
}

// ---------------- kernel 3: bf16 hi/lo split GEMM via mma.sync ----------------
__global__ __launch_bounds__(256)
void gemm_kernel(const float* __restrict__ h, float* __restrict__ out,
                 const float* __restrict__ bn, const float* __restrict__ bt) {
    __shared__ __align__(16) __nv_bfloat16 sAhi[BM * ASTR];
    __shared__ __align__(16) __nv_bfloat16 sAlo[BM * ASTR];
    __shared__ __align__(16) __nv_bfloat16 sBhi[N_COLS * BSTR];
    __shared__ __align__(16) __nv_bfloat16 sBlo[N_COLS * BSTR];
    __shared__ float s_bias[N_COLS];

    const int tid  = threadIdx.x;
    const int warp = tid >> 5;
    const int lane = tid & 31;
    const int wm   = warp & 3;       // m-tile of 32 rows
    const int wn   = warp >> 2;      // n-tile of 48 cols
    const int m0   = blockIdx.x * BM;

    if (tid < N_COLS) s_bias[tid] = (tid < N_ACT) ? bn[tid] : bt[tid - N_ACT];

    // A load coords: 2 threads per row, 16 consecutive floats each
    const int aRow = tid >> 1;
    const int aKh  = tid & 1;
    const float* gA = h + (size_t)(m0 + aRow) * ND + aKh * 16;

    // ldmatrix per-lane address pieces
    const uint32_t uAhi = smem_u32(sAhi);
    const uint32_t uAlo = smem_u32(sAlo);
    const uint32_t laneOff = (uint32_t)(((lane & 15) * ASTR + (lane >> 4) * 8) * 2);

    float acc[2][6][4];
    #pragma unroll
    for (int i = 0; i < 2; i++)
        #pragma unroll
        for (int j = 0; j < 6; j++)
            #pragma unroll
            for (int c = 0; c < 4; c++) acc[i][j][c] = 0.0f;

    // prefetch regs
    uint4 pah[2], pal[2];       // A hi/lo (16 bf16 each half)
    uint4 pbh[2], pbl[2];       // B hi/lo (tid < 192)

    // ---- prologue: load tile 0 ----
    split8(gA,     pah[0], pal[0]);
    split8(gA + 8, pah[1], pal[1]);
    if (tid < 192) {
        #pragma unroll
        for (int r = 0; r < 2; r++) {
            int idx = tid + 192 * r;
            int n = idx >> 2, q = idx & 3;
            pbh[r] = *(const uint4*)(g_Bhi + (size_t)n * ND + q * 8);
            pbl[r] = *(const uint4*)(g_Blo + (size_t)n * ND + q * 8);
        }
    }

    for (int t = 0; t < NTILES; t++) {
        __syncthreads();   // previous compute done before overwriting smem
        // ---- store tile t ----
        {
            __nv_bfloat16* dh = sAhi + aRow * ASTR + aKh * 16;
            __nv_bfloat16* dl = sAlo + aRow * ASTR + aKh * 16;
            *(uint4*)dh = pah[0]; *(uint4*)(dh + 8) = pah[1];
            *(uint4*)dl = pal[0]; *(uint4*)(dl + 8) = pal[1];
        }
        if (tid < 192) {
            #pragma unroll
            for (int r = 0; r < 2; r++) {
                int idx = tid + 192 * r;
                int n = idx >> 2, q = idx & 3;
                *(uint4*)(sBhi + n * BSTR + q * 8) = pbh[r];
                *(uint4*)(sBlo + n * BSTR + q * 8) = pbl[r];
            }
        }
        __syncthreads();

        // ---- prefetch tile t+1 ----
        if (t + 1 < NTILES) {
            const float* a2 = gA + (t + 1) * BK;
            split8(a2,     pah[0], pal[0]);
            split8(a2 + 8, pah[1], pal[1]);
            if (tid < 192) {
                #pragma unroll
                for (int r = 0; r < 2; r++) {
                    int idx = tid + 192 * r;
                    int n = idx >> 2, q = idx & 3;
                    const __nv_bfloat16* sh = g_Bhi + (size_t)n * ND + (t + 1) * BK + q * 8;
                    const __nv_bfloat16* sl = g_Blo + (size_t)n * ND + (t + 1) * BK + q * 8;
                    pbh[r] = *(const uint4*)sh;
                    pbl[r] = *(const uint4*)sl;
                }
            }
        }

        // ---- compute tile t: 2 k16 steps ----
        #pragma unroll
        for (int ks = 0; ks < 2; ks++) {
            uint32_t ah[2][4], al[2][4];
            #pragma unroll
            for (int mt = 0; mt < 2; mt++) {
                uint32_t rowBytes = (uint32_t)((wm * 32 + mt * 16) * ASTR * 2 + ks * 32);
                ldsm4(ah[mt], uAhi + rowBytes + laneOff);
                ldsm4(al[mt], uAlo + rowBytes + laneOff);
            }
            uint32_t bh[6][2], bl[6][2];
            #pragma unroll
            for (int j = 0; j < 6; j++) {
                int n = wn * 48 + j * 8 + (lane >> 2);
                int e = n * BSTR + (lane & 3) * 2 + ks * 16;
                bh[j][0] = *(const uint32_t*)(sBhi + e);
                bh[j][1] = *(const uint32_t*)(sBhi + e + 8);
                bl[j][0] = *(const uint32_t*)(sBlo + e);
                bl[j][1] = *(const uint32_t*)(sBlo + e + 8);
            }
            #pragma unroll
            for (int mt = 0; mt < 2; mt++)
                #pragma unroll
                for (int j = 0; j < 6; j++) {
                    mma_bf16(acc[mt][j], ah[mt], bh[j]);
                    mma_bf16(acc[mt][j], al[mt], bh[j]);
                    mma_bf16(acc[mt][j], ah[mt], bl[j]);
                }
        }
    }

    // ---- epilogue ----
    float* out_time = out + ACT_ELEMS;
    #pragma unroll
    for (int mt = 0; mt < 2; mt++) {
        size_t r0 = (size_t)m0 + wm * 32 + mt * 16 + (lane >> 2);
        size_t r1 = r0 + 8;
        #pragma unroll
        for (int j = 0; j < 6; j++) {
            int c0 = wn * 48 + j * 8 + (lane & 3) * 2;
            float b0 = s_bias[c0], b1 = s_bias[c0 + 1];
            float2 v0 = make_float2(acc[mt][j][0] + b0, acc[mt][j][1] + b1);
            float2 v1 = make_float2(acc[mt][j][2] + b0, acc[mt][j][3] + b1);
            if (c0 < N_ACT) {
                *(float2*)(out + r0 * N_ACT + c0) = v0;
                *(float2*)(out + r1 * N_ACT + c0) = v1;
            } else {
                int ct = c0 - N_ACT;
                *(float2*)(out_time + r0 * N_TIME + ct) = v0;
                *(float2*)(out_time + r1 * N_TIME + ct) = v1;
            }
        }
    }
}

// ---------------- kernel 4: retrieval/copy head, warp-per-key ----------------
__global__ __launch_bounds__(256)
void copy_kernel(const float* __restrict__ h, float* __restrict__ out,
                 const float* __restrict__ csa, const float* __restrict__ cst,
                 const float* __restrict__ cta, const float* __restrict__ ctt) {
    const int b    = blockIdx.y;
    const int tid  = threadIdx.x;
    const int warp = tid >> 5;
    const int lane = tid & 31;
    const int qcnt = g_qcnt[b];
    const int kc   = g_kcnt[b];

    __shared__ float s_acc[N_COLS];

    const float tau_a = softplus_f(*cta);
    const float tau_t = softplus_f(*ctt);
    const float sca   = softplus_f(*csa);
    const float sct   = softplus_f(*cst);
    const float* hb   = h + (size_t)b * NT_SEQ * ND;

    for (int qi = blockIdx.x; qi < qcnt; qi += gridDim.x) {
        __syncthreads();
        if (tid < N_COLS) s_acc[tid] = 0.0f;
        const int q = g_qlist[b][qi];
        const float rnq = g_qrn[b][qi];
        const float* hq = hb + (size_t)q * ND;
        float4 qv[8];
        #pragma unroll
        for (int c = 0; c < 8; c++) qv[c] = *(const float4*)(hq + c * 128 + lane * 4);
        __syncthreads();

        for (int j = warp; j < kc; j += 8) {
            int k = g_klist[b][j];
            if (k >= q) continue;
            const float* hk = hb + (size_t)k * ND;
            float dot = 0.0f;
            #pragma unroll
            for (int c = 0; c < 8; c++) {
                float4 kv = *(const float4*)(hk + c * 128 + lane * 4);
                dot += qv[c].x * kv.x + qv[c].y * kv.y + qv[c].z * kv.z + qv[c].w * kv.w;
            }
            #pragma unroll
            for (int o = 16; o; o >>= 1) dot += __shfl_xor_sync(0xffffffffu, dot, o);
            if (lane == 0) {
                int cls = g_kcls[b][j];
                float val = dot * rnq * g_krn[b][j] * (cls < N_ACT ? tau_a : tau_t);
                atomicAdd(&s_acc[cls], val);
            }
        }
        __syncthreads();

        size_t m = (size_t)b * NT_SEQ + q;
        if (tid < N_ACT) {
            out[m * N_ACT + tid] += sca * s_acc[tid];
        } else if (tid < N_COLS) {
            float* out_time = out + ACT_ELEMS;
            out_time[m * N_TIME + (tid - N_ACT)] += sct * s_acc[tid];
        }
    }
}

// ---------------- launch ----------------
extern "C" void kernel_launch(void* const* d_in, const int* in_sizes, int n_in,
                              void* d_out, int out_size) {
    const int*   tokens = (const int*)  d_in[0];
    const float* h      = (const float*)d_in[1];
    const float* E      = (const float*)d_in[2];
    const float* Wn     = (const float*)d_in[3];
    const float* bn     = (const float*)d_in[4];
    const float* Wt     = (const float*)d_in[5];
    const float* bt     = (const float*)d_in[6];
    const float* tsa    = (const float*)d_in[7];
    const float* tst    = (const float*)d_in[8];
    const float* csa    = (const float*)d_in[9];
    const float* cst    = (const float*)d_in[10];
    const float* cta    = (const float*)d_in[11];
    const float* ctt    = (const float*)d_in[12];
    float* out = (float*)d_out;

    prep_kernel<<<WC_BLOCKS + NB, 256>>>(E, Wn, Wt, tsa, tst, tokens);
    norm_kernel<<<dim3(256, NB), 32>>>(h);
    gemm_kernel<<<M_TOT / BM, 256>>>(h, out, bn, bt);
    copy_kernel<<<dim3(64, NB), 256>>>(h, out, csa, cst, cta, ctt);
}

// round 7
// speedup vs baseline: 2.8706x; 2.1789x over previous
#include <cuda_runtime.h>
#include <cuda_fp16.h>
#include <cstdint>

// ---------------- problem constants ----------------
#define TOK_LABEL   2
#define ACT_START   5
#define TIME_START  69
#define NB          8
#define NT_SEQ      2048
#define ND          1024
#define N_ACT       64
#define N_TIME      32
#define N_COLS      96
#define M_TOT       (NB * NT_SEQ)
#define ACT_ELEMS   ((size_t)M_TOT * N_ACT)

// GEMM tiling
#define BM       64
#define BK       64
#define NTILES   (ND / BK)     // 16
#define ASTR     72            // smem row stride in halves
#define BSTR     72

// ---------------- scratch ----------------
__device__ __align__(16) __half g_Bh[N_COLS * ND];   // folded weights, fp16
__device__ int   g_qlist[NB][NT_SEQ];
__device__ int   g_klist[NB][NT_SEQ];
__device__ int   g_kcls [NB][NT_SEQ];
__device__ int   g_qcnt[NB];
__device__ int   g_kcnt[NB];

// ---------------- helpers ----------------
__device__ __forceinline__ float softplus_f(float x) {
    return (x > 20.0f) ? x : log1pf(expf(x));
}
__device__ __forceinline__ uint32_t smem_u32(const void* p) {
    uint32_t a;
    asm("{ .reg .u64 t; cvta.to.shared.u64 t, %1; cvt.u32.u64 %0, t; }" : "=r"(a) : "l"(p));
    return a;
}
__device__ __forceinline__ void ldsm4(uint32_t* r, uint32_t addr) {
    asm volatile("ldmatrix.sync.aligned.m8n8.x4.shared.b16 {%0,%1,%2,%3}, [%4];"
                 : "=r"(r[0]), "=r"(r[1]), "=r"(r[2]), "=r"(r[3]) : "r"(addr));
}
__device__ __forceinline__ void mma_f16(float* c, const uint32_t* a, const uint32_t* b) {
    asm volatile(
        "mma.sync.aligned.m16n8k16.row.col.f32.f16.f16.f32 "
        "{%0,%1,%2,%3}, {%4,%5,%6,%7}, {%8,%9}, {%0,%1,%2,%3};"
        : "+f"(c[0]), "+f"(c[1]), "+f"(c[2]), "+f"(c[3])
        : "r"(a[0]), "r"(a[1]), "r"(a[2]), "r"(a[3]), "r"(b[0]), "r"(b[1]));
}
// convert 16 fp32 -> 16 fp16 packed into 2 uint4
__device__ __forceinline__ void cvt16(const float4* f, uint4& o0, uint4& o1) {
    uint32_t u[8];
    #pragma unroll
    for (int i = 0; i < 4; i++) {
        __half2 a = __float22half2_rn(make_float2(f[i].x, f[i].y));
        __half2 b = __float22half2_rn(make_float2(f[i].z, f[i].w));
        u[2 * i]     = *(uint32_t*)&a;
        u[2 * i + 1] = *(uint32_t*)&b;
    }
    o0 = make_uint4(u[0], u[1], u[2], u[3]);
    o1 = make_uint4(u[4], u[5], u[6], u[7]);
}

// ---------------- kernel 1: weight-fold (-> fp16) + token scan ----------------
#define WC_BLOCKS 384   // 96*1024 / 256

__global__ void prep_kernel(const float* __restrict__ E,
                            const float* __restrict__ Wn,
                            const float* __restrict__ Wt,
                            const float* __restrict__ tsa, const float* __restrict__ tst,
                            const int* __restrict__ tokens) {
    if (blockIdx.x < WC_BLOCKS) {
        int i = blockIdx.x * blockDim.x + threadIdx.x;
        float sa = softplus_f(*tsa);
        float st = softplus_f(*tst);
        int r = i >> 10;
        int c = i & (ND - 1);
        float v;
        if (r < N_ACT)
            v = Wn[r * ND + c] + sa * E[(ACT_START + r) * ND + c];
        else
            v = Wt[(r - N_ACT) * ND + c] + st * E[(TIME_START + (r - N_ACT)) * ND + c];
        g_Bh[i] = __float2half_rn(v);
        return;
    }
    int b    = blockIdx.x - WC_BLOCKS;
    int lane = threadIdx.x & 31;
    int warp = threadIdx.x >> 5;
    const int* tk = tokens + b * NT_SEQ;

    if (warp == 0) {
        int cnt = 0;
        for (int base = 0; base < NT_SEQ; base += 32) {
            int pos = base + lane;
            bool p = (tk[pos] == TOK_LABEL);
            unsigned m = __ballot_sync(0xffffffffu, p);
            if (p) g_qlist[b][cnt + __popc(m & ((1u << lane) - 1u))] = pos;
            cnt += __popc(m);
        }
        if (lane == 0) g_qcnt[b] = cnt;
    } else if (warp == 1) {
        int cnt = 0;
        for (int base = 0; base < NT_SEQ; base += 32) {
            int pos = base + lane;
            int tok = tk[pos];
            bool p = (pos >= 1) && (tk[pos - 1] == TOK_LABEL) && (tok >= ACT_START);
            unsigned m = __ballot_sync(0xffffffffu, p);
            if (p) {
                int r = cnt + __popc(m & ((1u << lane) - 1u));
                g_klist[b][r] = pos;
                g_kcls[b][r]  = (tok < TIME_START) ? (tok - ACT_START)
                                                   : (N_ACT + (tok - TIME_START));
            }
            cnt += __popc(m);
        }
        if (lane == 0) g_kcnt[b] = cnt;
    }
}

// ---------------- kernel 2: fp16 GEMM via mma.sync (m32xn24 warp tiles) ----------------
__global__ __launch_bounds__(256, 2)
void gemm_kernel(const float* __restrict__ h, float* __restrict__ out,
                 const float* __restrict__ bn, const float* __restrict__ bt) {
    __shared__ __align__(16) __half sA[2][BM * ASTR];       // 2 x 9216 B
    __shared__ __align__(16) __half sB[2][N_COLS * BSTR];   // 2 x 13824 B
    __shared__ float s_bias[N_COLS];

    const int tid  = threadIdx.x;
    const int warp = tid >> 5;
    const int lane = tid & 31;
    const int wm   = warp & 1;       // m-tile of 32
    const int wn   = warp >> 1;      // n-tile of 24
    const int m0   = blockIdx.x * BM;

    if (tid < N_COLS) s_bias[tid] = (tid < N_ACT) ? bn[tid] : bt[tid - N_ACT];

    // A: 64 rows x 64 k fp32 per tile; 4 threads/row x 16 floats
    const int aRow = tid >> 2;
    const int aK   = (tid & 3) * 16;
    const float* gA = h + (size_t)(m0 + aRow) * ND + aK;

    // B: 96 rows x 64 halves per tile; threads 0..191, 2/row x 32 halves
    const int bN = tid >> 1;
    const int bK = (tid & 1) * 32;
    const __half* gB = g_Bh + (size_t)bN * ND + bK;

    float acc[2][3][4];
    #pragma unroll
    for (int i = 0; i < 2; i++)
        #pragma unroll
        for (int j = 0; j < 3; j++)
            #pragma unroll
            for (int c = 0; c < 4; c++) acc[i][j][c] = 0.0f;

    float4 fa[4];
    uint4  pb[4];

    // ---- prologue: tile 0 load + store to stage 0 ----
    #pragma unroll
    for (int i = 0; i < 4; i++) fa[i] = *(const float4*)(gA + 4 * i);
    if (tid < 192)
        #pragma unroll
        for (int i = 0; i < 4; i++) pb[i] = *(const uint4*)(gB + 8 * i);
    {
        uint4 o0, o1; cvt16(fa, o0, o1);
        __half* dA = &sA[0][aRow * ASTR + aK];
        *(uint4*)dA = o0; *(uint4*)(dA + 8) = o1;
        if (tid < 192) {
            __half* dB = &sB[0][bN * BSTR + bK];
            #pragma unroll
            for (int i = 0; i < 4; i++) *(uint4*)(dB + 8 * i) = pb[i];
        }
    }
    __syncthreads();

    const uint32_t uA0 = smem_u32(&sA[0][0]);
    const uint32_t uA1 = smem_u32(&sA[1][0]);
    const uint32_t aoff0 = (uint32_t)(((wm * 32 +      (lane & 15)) * ASTR + (lane >> 4) * 8) * 2);
    const uint32_t aoff1 = (uint32_t)(((wm * 32 + 16 + (lane & 15)) * ASTR + (lane >> 4) * 8) * 2);

    for (int t = 0; t < NTILES; t++) {
        const int cur = t & 1;
        // ---- prefetch tile t+1 into regs ----
        if (t + 1 < NTILES) {
            const float* a2 = gA + (t + 1) * BK;
            #pragma unroll
            for (int i = 0; i < 4; i++) fa[i] = *(const float4*)(a2 + 4 * i);
            if (tid < 192) {
                const __half* b2 = gB + (t + 1) * BK;
                #pragma unroll
                for (int i = 0; i < 4; i++) pb[i] = *(const uint4*)(b2 + 8 * i);
            }
        }

        // ---- compute current tile: 4 k16 steps ----
        const uint32_t uA = cur ? uA1 : uA0;
        const __half* sb = &sB[cur][0];
        #pragma unroll
        for (int ks = 0; ks < 4; ks++) {
            uint32_t a0[4], a1[4];
            ldsm4(a0, uA + aoff0 + ks * 32);
            ldsm4(a1, uA + aoff1 + ks * 32);
            uint32_t b[3][2];
            #pragma unroll
            for (int j = 0; j < 3; j++) {
                int n = wn * 24 + j * 8 + (lane >> 2);
                const __half* p = sb + n * BSTR + ks * 16 + (lane & 3) * 2;
                b[j][0] = *(const uint32_t*)p;
                b[j][1] = *(const uint32_t*)(p + 8);
            }
            #pragma unroll
            for (int j = 0; j < 3; j++) {
                mma_f16(acc[0][j], a0, b[j]);
                mma_f16(acc[1][j], a1, b[j]);
            }
        }

        // ---- store prefetched tile into other stage ----
        if (t + 1 < NTILES) {
            const int nxt = cur ^ 1;
            uint4 o0, o1; cvt16(fa, o0, o1);
            __half* dA = &sA[nxt][aRow * ASTR + aK];
            *(uint4*)dA = o0; *(uint4*)(dA + 8) = o1;
            if (tid < 192) {
                __half* dB = &sB[nxt][bN * BSTR + bK];
                #pragma unroll
                for (int i = 0; i < 4; i++) *(uint4*)(dB + 8 * i) = pb[i];
            }
        }
        __syncthreads();
    }

    // ---- epilogue ----
    float* out_time = out + ACT_ELEMS;
    #pragma unroll
    for (int mt = 0; mt < 2; mt++) {
        size_t r0 = (size_t)m0 + wm * 32 + mt * 16 + (lane >> 2);
        size_t r1 = r0 + 8;
        #pragma unroll
        for (int j = 0; j < 3; j++) {
            int c0 = wn * 24 + j * 8 + (lane & 3) * 2;
            float b0 = s_bias[c0], b1 = s_bias[c0 + 1];
            float2 v0 = make_float2(acc[mt][j][0] + b0, acc[mt][j][1] + b1);
            float2 v1 = make_float2(acc[mt][j][2] + b0, acc[mt][j][3] + b1);
            if (c0 < N_ACT) {
                *(float2*)(out + r0 * N_ACT + c0) = v0;
                *(float2*)(out + r1 * N_ACT + c0) = v1;
            } else {
                int ct = c0 - N_ACT;
                *(float2*)(out_time + r0 * N_TIME + ct) = v0;
                *(float2*)(out_time + r1 * N_TIME + ct) = v1;
            }
        }
    }
}

// ---------------- kernel 3: retrieval/copy head (per-warp norms — FIXED) ----------------
__global__ __launch_bounds__(256)
void copy_kernel(const float* __restrict__ h, float* __restrict__ out,
                 const float* __restrict__ csa, const float* __restrict__ cst,
                 const float* __restrict__ cta, const float* __restrict__ ctt) {
    const int b    = blockIdx.y;
    const int tid  = threadIdx.x;
    const int warp = tid >> 5;
    const int lane = tid & 31;
    const int qcnt = g_qcnt[b];
    const int kc   = g_kcnt[b];

    __shared__ float s_acc[N_COLS];

    const float tau_a = softplus_f(*cta);
    const float tau_t = softplus_f(*ctt);
    const float sca   = softplus_f(*csa);
    const float sct   = softplus_f(*cst);
    const float* hb   = h + (size_t)b * NT_SEQ * ND;

    for (int qi = blockIdx.x; qi < qcnt; qi += gridDim.x) {
        __syncthreads();                 // prev iteration's reads of s_acc done
        if (tid < N_COLS) s_acc[tid] = 0.0f;
        const int q = g_qlist[b][qi];
        const float* hq = hb + (size_t)q * ND;
        float4 qv[8];
        float nq = 0.0f;
        #pragma unroll
        for (int c = 0; c < 8; c++) {
            qv[c] = *(const float4*)(hq + c * 128 + lane * 4);
            nq += qv[c].x*qv[c].x + qv[c].y*qv[c].y + qv[c].z*qv[c].z + qv[c].w*qv[c].w;
        }
        #pragma unroll
        for (int o = 16; o; o >>= 1) nq += __shfl_xor_sync(0xffffffffu, nq, o);
        // each warp's 32 lanes cover the full 1024-dim row, so nq == ||q||^2 already
        const float rnq = 1.0f / fmaxf(sqrtf(nq), 1e-12f);
        __syncthreads();                 // s_acc zeroing visible before atomics

        // 2 keys per warp per round for memory-level parallelism
        for (int j = warp; j < kc; j += 16) {
            const int jb = j + 8;
            const bool h2 = jb < kc;
            int k1 = g_klist[b][j];
            int k2 = h2 ? g_klist[b][jb] : k1;
            bool m1 = (k1 < q);
            bool m2 = h2 && (k2 < q);
            if (!m1 && !m2) continue;
            const float* p1 = hb + (size_t)k1 * ND;
            const float* p2 = hb + (size_t)k2 * ND;
            float d1 = 0.0f, n1 = 0.0f, d2 = 0.0f, n2 = 0.0f;
            #pragma unroll
            for (int c = 0; c < 8; c++) {
                float4 a = *(const float4*)(p1 + c * 128 + lane * 4);
                float4 v = *(const float4*)(p2 + c * 128 + lane * 4);
                d1 += qv[c].x*a.x + qv[c].y*a.y + qv[c].z*a.z + qv[c].w*a.w;
                n1 += a.x*a.x + a.y*a.y + a.z*a.z + a.w*a.w;
                d2 += qv[c].x*v.x + qv[c].y*v.y + qv[c].z*v.z + qv[c].w*v.w;
                n2 += v.x*v.x + v.y*v.y + v.z*v.z + v.w*v.w;
            }
            #pragma unroll
            for (int o = 16; o; o >>= 1) {
                d1 += __shfl_xor_sync(0xffffffffu, d1, o);
                n1 += __shfl_xor_sync(0xffffffffu, n1, o);
                d2 += __shfl_xor_sync(0xffffffffu, d2, o);
                n2 += __shfl_xor_sync(0xffffffffu, n2, o);
            }
            if (lane == 0) {
                if (m1) {
                    int cls = g_kcls[b][j];
                    float sim = d1 * rnq / fmaxf(sqrtf(n1), 1e-12f);
                    atomicAdd(&s_acc[cls], sim * (cls < N_ACT ? tau_a : tau_t));
                }
                if (m2) {
                    int cls = g_kcls[b][jb];
                    float sim = d2 * rnq / fmaxf(sqrtf(n2), 1e-12f);
                    atomicAdd(&s_acc[cls], sim * (cls < N_ACT ? tau_a : tau_t));
                }
            }
        }
        __syncthreads();

        size_t m = (size_t)b * NT_SEQ + q;
        if (tid < N_ACT) {
            out[m * N_ACT + tid] += sca * s_acc[tid];
        } else if (tid < N_COLS) {
            float* out_time = out + ACT_ELEMS;
            out_time[m * N_TIME + (tid - N_ACT)] += sct * s_acc[tid];
        }
    }
}

// ---------------- launch ----------------
extern "C" void kernel_launch(void* const* d_in, const int* in_sizes, int n_in,
                              void* d_out, int out_size) {
    const int*   tokens = (const int*)  d_in[0];
    const float* h      = (const float*)d_in[1];
    const float* E      = (const float*)d_in[2];
    const float* Wn     = (const float*)d_in[3];
    const float* bn     = (const float*)d_in[4];
    const float* Wt     = (const float*)d_in[5];
    const float* bt     = (const float*)d_in[6];
    const float* tsa    = (const float*)d_in[7];
    const float* tst    = (const float*)d_in[8];
    const float* csa    = (const float*)d_in[9];
    const float* cst    = (const float*)d_in[10];
    const float* cta    = (const float*)d_in[11];
    const float* ctt    = (const float*)d_in[12];
    float* out = (float*)d_out;

    prep_kernel<<<WC_BLOCKS + NB, 256>>>(E, Wn, Wt, tsa, tst, tokens);
    gemm_kernel<<<M_TOT / BM, 256>>>(h, out, bn, bt);
    copy_kernel<<<dim3(48, NB), 256>>>(h, out, csa, cst, cta, ctt);
}